// round 9
// baseline (speedup 1.0000x reference)
#include <cuda_runtime.h>
#include <cuda_fp16.h>
#include <cstdint>

// Problem constants
#define S_TOK   4096
#define NSLOT   8192
#define DM      768
#define DF      3072
#define NE      8

#define BM 128
#define BN 256
#define BK 64
#define ASTR 72            // A smem stride in halves (144B rows)
#define BSTR 264           // B smem stride in halves (528B rows, 33x16B: odd -> conflict-free)

// ---- scratch (device globals; no allocation allowed) ----
__device__ int    g_count[NE];
__device__ int    g_list[NE][NSLOT];
__device__ float  g_sw[NSLOT];                    // per-slot combine weight
__device__ __half g_xh[(size_t)S_TOK * DM];
__device__ __half g_w1h[(size_t)NE * DM * DF];
__device__ __half g_w2h[(size_t)NE * DF * DM];
__device__ __half g_h[(size_t)NSLOT * DF];

// ---------------------------------------------------------------------------
// prep: zero out + zero counts + all three f2h converts, one launch
// ---------------------------------------------------------------------------
#define N_OUT4 (S_TOK * DM / 4)
#define NX4    (S_TOK * DM / 4)
#define NW4    (NE * DM * DF / 4)
#define PREP_ITEMS (N_OUT4 + NX4 + 2 * NW4)

__device__ __forceinline__ uint2 cvt4(const float4 v) {
    __half2 a = __floats2half2_rn(v.x, v.y);
    __half2 b = __floats2half2_rn(v.z, v.w);
    uint2 pk;
    pk.x = *(const unsigned*)&a;
    pk.y = *(const unsigned*)&b;
    return pk;
}

__global__ void __launch_bounds__(256) prep_kernel(float* __restrict__ out,
                                                   const float* __restrict__ x,
                                                   const float* __restrict__ W1,
                                                   const float* __restrict__ W2) {
    int i = blockIdx.x * blockDim.x + threadIdx.x;
    if (blockIdx.x == 0 && threadIdx.x < NE) g_count[threadIdx.x] = 0;
    if (i < N_OUT4) {
        ((float4*)out)[i] = make_float4(0.f, 0.f, 0.f, 0.f);
        return;
    }
    i -= N_OUT4;
    if (i < NX4) {
        ((uint2*)g_xh)[i] = cvt4(((const float4*)x)[i]);
        return;
    }
    i -= NX4;
    if (i < NW4) {
        ((uint2*)g_w1h)[i] = cvt4(((const float4*)W1)[i]);
        return;
    }
    i -= NW4;
    if (i < NW4) {
        ((uint2*)g_w2h)[i] = cvt4(((const float4*)W2)[i]);
    }
}

// ---------------------------------------------------------------------------
// gate: warp per token
// ---------------------------------------------------------------------------
__global__ void __launch_bounds__(256) gate_kernel(const float* __restrict__ x,
                                                   const float* __restrict__ Wg) {
    int warp = threadIdx.x >> 5;
    int lane = threadIdx.x & 31;
    int s = blockIdx.x * 8 + warp;
    if (s >= S_TOK) return;

    const float* xr = x + (size_t)s * DM;
    float acc[NE];
#pragma unroll
    for (int e = 0; e < NE; e++) acc[e] = 0.f;

    for (int m = lane; m < DM; m += 32) {
        float xv = xr[m];
        const float* wr = Wg + m * NE;
#pragma unroll
        for (int e = 0; e < NE; e++) acc[e] += xv * wr[e];
    }
#pragma unroll
    for (int e = 0; e < NE; e++) {
#pragma unroll
        for (int o = 16; o > 0; o >>= 1) {
            acc[e] += __shfl_xor_sync(0xffffffffu, acc[e], o);
        }
    }

    if (lane == 0) {
        int a = 0;
#pragma unroll
        for (int e = 1; e < NE; e++) {
            if (acc[e] > acc[a]) a = e;
        }
        int b = (a == 0) ? 1 : 0;
#pragma unroll
        for (int e = 0; e < NE; e++) {
            if (e != a && acc[e] > acc[b]) b = e;
        }

        float eb = __expf(acc[b] - acc[a]);
        float inv = 1.f / (1.f + eb);
        g_sw[s] = inv;
        g_sw[S_TOK + s] = eb * inv;

        int pa = atomicAdd(&g_count[a], 1);
        g_list[a][pa] = s;
        int pb = atomicAdd(&g_count[b], 1);
        g_list[b][pb] = S_TOK + s;
    }
}

// ---------------------------------------------------------------------------
// tensor-core + cp.async helpers
// ---------------------------------------------------------------------------
__device__ __forceinline__ void ldsm_x4(unsigned& r0, unsigned& r1,
                                        unsigned& r2, unsigned& r3,
                                        const void* p) {
    unsigned a = (unsigned)__cvta_generic_to_shared(p);
    asm volatile("ldmatrix.sync.aligned.m8n8.x4.shared.b16 {%0,%1,%2,%3}, [%4];\n"
                 : "=r"(r0), "=r"(r1), "=r"(r2), "=r"(r3) : "r"(a));
}

__device__ __forceinline__ void ldsm_x4_t(unsigned& r0, unsigned& r1,
                                          unsigned& r2, unsigned& r3,
                                          const void* p) {
    unsigned a = (unsigned)__cvta_generic_to_shared(p);
    asm volatile("ldmatrix.sync.aligned.m8n8.x4.trans.shared.b16 {%0,%1,%2,%3}, [%4];\n"
                 : "=r"(r0), "=r"(r1), "=r"(r2), "=r"(r3) : "r"(a));
}

__device__ __forceinline__ void mma16816(float* c, const unsigned* a, const unsigned* b) {
    asm volatile(
        "mma.sync.aligned.m16n8k16.row.col.f32.f16.f16.f32 "
        "{%0,%1,%2,%3}, {%4,%5,%6,%7}, {%8,%9}, {%0,%1,%2,%3};\n"
        : "+f"(c[0]), "+f"(c[1]), "+f"(c[2]), "+f"(c[3])
        : "r"(a[0]), "r"(a[1]), "r"(a[2]), "r"(a[3]), "r"(b[0]), "r"(b[1]));
}

__device__ __forceinline__ void cp_async16(void* smem_ptr, const void* gptr, bool valid) {
    unsigned saddr = (unsigned)__cvta_generic_to_shared(smem_ptr);
    int sz = valid ? 16 : 0;
    asm volatile("cp.async.cg.shared.global [%0], [%1], 16, %2;\n"
                 :: "r"(saddr), "l"(gptr), "r"(sz));
}
__device__ __forceinline__ void cp_commit() {
    asm volatile("cp.async.commit_group;\n");
}
template<int N>
__device__ __forceinline__ void cp_wait() {
    asm volatile("cp.async.wait_group %0;\n" :: "n"(N));
}

// ---------------------------------------------------------------------------
// Grouped GEMM, 128x256x64 CTA tile, 64x64 warp tiles (2x4), 3-stage pipeline.
//   GEMM1: A = g_xh[slot & (S-1)], W = g_w1h -> relu -> g_h (half)
//   GEMM2: A = g_h[slot],          W = g_w2h -> w*(.+b2) atomicAdd -> out
// grid (NDIM/BN, NSLOT/BM, NE), 256 threads
// ---------------------------------------------------------------------------
template<int KDIM, int NDIM, bool GEMM1>
__global__ void __launch_bounds__(256, 1) moe_gemm(const float* __restrict__ bias,
                                                   float* __restrict__ out) {
    constexpr int A_ST_ELEM = BM * ASTR;
    constexpr int B_ST_ELEM = BK * BSTR;

    const int e = blockIdx.z;
    const int cnt = g_count[e];
    const int row0 = blockIdx.y * BM;
    if (row0 >= cnt) return;
    const int f0 = blockIdx.x * BN;

    extern __shared__ __half dyn[];
    __half* Asb = dyn;                        // [3][BM][ASTR]
    __half* Bsb = dyn + 3 * A_ST_ELEM;        // [3][BK][BSTR]
    __shared__ int rows_s[BM];

    const int tid = threadIdx.x;
    const int lane = tid & 31;
    const int wid = tid >> 5;
    const int wm = (wid >> 2) * 64;           // 2 warp rows
    const int wn = (wid & 3) * 64;            // 4 warp cols

    if (tid < BM) {
        int r = row0 + tid;
        rows_s[tid] = (r < cnt) ? g_list[e][r] : -1;
    }
    __syncthreads();

    const __half* Ab = GEMM1 ? g_xh : g_h;
    const __half* Wb = (GEMM1 ? g_w1h : g_w2h) + (size_t)e * KDIM * NDIM;

    // per-thread load coords
    // A: 1024 chunks (128 rows x 8 chunks); 4 per thread
    int a_r[4], a_kq[4], a_slot[4];
#pragma unroll
    for (int l = 0; l < 4; l++) {
        int u = tid + l * 256;
        a_r[l] = u >> 3;
        a_kq[l] = u & 7;
        a_slot[l] = rows_s[a_r[l]];
    }
    // B: 64 k-rows x 32 chunks; 8 per thread
    int b_kr[8], b_cq[8];
#pragma unroll
    for (int l = 0; l < 8; l++) {
        int u = tid + l * 256;
        b_kr[l] = u >> 5;
        b_cq[l] = u & 31;
    }

    const int NK = KDIM / BK;

    auto load_tile = [&](int buf, int kt) {
        __half* As = Asb + buf * A_ST_ELEM;
        __half* Bs = Bsb + buf * B_ST_ELEM;
#pragma unroll
        for (int l = 0; l < 4; l++) {
            int slot = a_slot[l];
            const __half* src = Ab;
            bool v = (slot >= 0);
            if (v) {
                int arow = GEMM1 ? (slot & (S_TOK - 1)) : slot;
                src = Ab + (size_t)arow * KDIM + kt + a_kq[l] * 8;
            }
            cp_async16(As + a_r[l] * ASTR + a_kq[l] * 8, src, v);
        }
#pragma unroll
        for (int l = 0; l < 8; l++) {
            const __half* src = Wb + (size_t)(kt + b_kr[l]) * NDIM + f0 + b_cq[l] * 8;
            cp_async16(Bs + b_kr[l] * BSTR + b_cq[l] * 8, src, true);
        }
    };

    float c[4][8][4];
#pragma unroll
    for (int mi = 0; mi < 4; mi++) {
#pragma unroll
        for (int ni = 0; ni < 8; ni++) {
#pragma unroll
            for (int q = 0; q < 4; q++) {
                c[mi][ni][q] = 0.f;
            }
        }
    }

    load_tile(0, 0);
    cp_commit();
    load_tile(1, BK);
    cp_commit();

    for (int k = 0; k < NK; k++) {
        cp_wait<1>();            // tile k resident (tile k+1 may still fly)
        __syncthreads();

        if (k + 2 < NK) {
            load_tile((k + 2) % 3, (k + 2) * BK);   // overwrites tile k-1's buffer
        }
        cp_commit();

        const int buf = k % 3;
        const __half* As = Asb + buf * A_ST_ELEM;
        const __half* Bs = Bsb + buf * B_ST_ELEM;

#pragma unroll
        for (int kc = 0; kc < BK; kc += 16) {
            unsigned af[4][4];
            unsigned bf[8][2];
#pragma unroll
            for (int mi = 0; mi < 4; mi++) {
                ldsm_x4(af[mi][0], af[mi][1], af[mi][2], af[mi][3],
                        As + (wm + mi * 16 + (lane & 15)) * ASTR + kc + (lane >> 4) * 8);
            }
#pragma unroll
            for (int nj = 0; nj < 4; nj++) {
                ldsm_x4_t(bf[2 * nj][0], bf[2 * nj][1],
                          bf[2 * nj + 1][0], bf[2 * nj + 1][1],
                          Bs + (kc + (lane & 15)) * BSTR + wn + nj * 16 + (lane >> 4) * 8);
            }
#pragma unroll
            for (int mi = 0; mi < 4; mi++) {
#pragma unroll
                for (int ni = 0; ni < 8; ni++) {
                    mma16816(c[mi][ni], af[mi], bf[ni]);
                }
            }
        }
    }

    // epilogue
    const float* be = bias + (size_t)e * NDIM + f0;
    float bias0[8];
    float bias1[8];
#pragma unroll
    for (int ni = 0; ni < 8; ni++) {
        int col = wn + ni * 8 + (lane & 3) * 2;
        bias0[ni] = be[col];
        bias1[ni] = be[col + 1];
    }
#pragma unroll
    for (int mi = 0; mi < 4; mi++) {
#pragma unroll
        for (int hr = 0; hr < 2; hr++) {
            int rr = wm + mi * 16 + hr * 8 + (lane >> 2);
            int slot = rows_s[rr];
            if (slot >= 0) {
                if (GEMM1) {
                    __half* hp = g_h + (size_t)slot * NDIM + f0;
#pragma unroll
                    for (int ni = 0; ni < 8; ni++) {
                        int col = wn + ni * 8 + (lane & 3) * 2;
                        float v0 = fmaxf(c[mi][ni][hr * 2 + 0] + bias0[ni], 0.f);
                        float v1 = fmaxf(c[mi][ni][hr * 2 + 1] + bias1[ni], 0.f);
                        *(__half2*)(hp + col) = __floats2half2_rn(v0, v1);
                    }
                } else {
                    int tok = slot & (S_TOK - 1);
                    float w = g_sw[slot];
                    float* op = out + (size_t)tok * DM + f0;
#pragma unroll
                    for (int ni = 0; ni < 8; ni++) {
                        int col = wn + ni * 8 + (lane & 3) * 2;
                        atomicAdd(op + col,     w * (c[mi][ni][hr * 2 + 0] + bias0[ni]));
                        atomicAdd(op + col + 1, w * (c[mi][ni][hr * 2 + 1] + bias1[ni]));
                    }
                }
            }
        }
    }
}

// ---------------------------------------------------------------------------
extern "C" void kernel_launch(void* const* d_in, const int* in_sizes, int n_in,
                              void* d_out, int out_size) {
    const float* x  = (const float*)d_in[0];
    const float* Wg = (const float*)d_in[1];
    const float* W1 = (const float*)d_in[2];
    const float* b1 = (const float*)d_in[3];
    const float* W2 = (const float*)d_in[4];
    const float* b2 = (const float*)d_in[5];
    float* out = (float*)d_out;

    // dynamic smem: 3 stages x (A + B) halves -> bytes
    const int smem = 3 * (BM * ASTR + BK * BSTR) * 2;   // 156,672 B
    cudaFuncSetAttribute((const void*)moe_gemm<DM, DF, true>,
                         cudaFuncAttributeMaxDynamicSharedMemorySize, smem);
    cudaFuncSetAttribute((const void*)moe_gemm<DF, DM, false>,
                         cudaFuncAttributeMaxDynamicSharedMemorySize, smem);

    prep_kernel<<<(PREP_ITEMS + 255) / 256, 256>>>(out, x, W1, W2);
    gate_kernel<<<S_TOK / 8, 256>>>(x, Wg);
    moe_gemm<DM, DF, true ><<<dim3(DF / BN, NSLOT / BM, NE), 256, smem>>>(b1, out);
    moe_gemm<DF, DM, false><<<dim3(DM / BN, NSLOT / BM, NE), 256, smem>>>(b2, out);
}

// round 10
// speedup vs baseline: 1.2609x; 1.2609x over previous
#include <cuda_runtime.h>
#include <cuda_fp16.h>
#include <cstdint>

// Problem constants
#define S_TOK   4096
#define NSLOT   8192
#define DM      768
#define DF      3072
#define NE      8

#define BM 128
#define BN 128
#define BK 64
#define ASTR 72            // A smem stride in halves
#define BSTR 136           // B smem stride in halves

#define N_OUT4 (S_TOK * DM / 4)
#define NX4    (S_TOK * DM / 4)
#define NW4    (NE * DM * DF / 4)

#define GATE_BLKS 512
#define CONV_BLKS 6144
#define W2_XTRA   4        // extra grid-x tiles on GEMM1 for W2 conversion

// ---- scratch (device globals; no allocation allowed) ----
__device__ int    g_count[NE];
__device__ int    g_list[NE][NSLOT];
__device__ float  g_sw[NSLOT];
__device__ __half g_xh[(size_t)S_TOK * DM];
__device__ __half g_w1h[(size_t)NE * DM * DF];
__device__ __half g_w2h[(size_t)NE * DF * DM];
__device__ __half g_h[(size_t)NSLOT * DF];

// ---------------------------------------------------------------------------
__global__ void zero_counts_kernel() {
    if (threadIdx.x < NE) g_count[threadIdx.x] = 0;
}

__device__ __forceinline__ uint2 cvt4(const float4 v) {
    __half2 a = __floats2half2_rn(v.x, v.y);
    __half2 b = __floats2half2_rn(v.z, v.w);
    uint2 pk;
    pk.x = *(const unsigned*)&a;
    pk.y = *(const unsigned*)&b;
    return pk;
}

// ---------------------------------------------------------------------------
// fused gate + (zero out, convert x, convert W1)
//   blocks [0, GATE_BLKS): gate (warp per token)
//   blocks [GATE_BLKS, GATE_BLKS+CONV_BLKS): grid-stride conversion work
// ---------------------------------------------------------------------------
__global__ void __launch_bounds__(256) gate_prep_kernel(const float* __restrict__ x,
                                                        const float* __restrict__ Wg,
                                                        const float* __restrict__ W1,
                                                        float* __restrict__ out) {
    if (blockIdx.x >= GATE_BLKS) {
        const int cb = blockIdx.x - GATE_BLKS;
        const int t0 = cb * 256 + threadIdx.x;
        const int NT = CONV_BLKS * 256;
        for (int i = t0; i < N_OUT4; i += NT) {
            ((float4*)out)[i] = make_float4(0.f, 0.f, 0.f, 0.f);
        }
        for (int i = t0; i < NX4; i += NT) {
            ((uint2*)g_xh)[i] = cvt4(((const float4*)x)[i]);
        }
        for (int i = t0; i < NW4; i += NT) {
            ((uint2*)g_w1h)[i] = cvt4(((const float4*)W1)[i]);
        }
        return;
    }

    int warp = threadIdx.x >> 5;
    int lane = threadIdx.x & 31;
    int s = blockIdx.x * 8 + warp;
    if (s >= S_TOK) return;

    const float* xr = x + (size_t)s * DM;
    float acc[NE];
#pragma unroll
    for (int e = 0; e < NE; e++) acc[e] = 0.f;

    for (int m = lane; m < DM; m += 32) {
        float xv = xr[m];
        const float* wr = Wg + m * NE;
#pragma unroll
        for (int e = 0; e < NE; e++) acc[e] += xv * wr[e];
    }
#pragma unroll
    for (int e = 0; e < NE; e++) {
#pragma unroll
        for (int o = 16; o > 0; o >>= 1) {
            acc[e] += __shfl_xor_sync(0xffffffffu, acc[e], o);
        }
    }

    if (lane == 0) {
        int a = 0;
#pragma unroll
        for (int e = 1; e < NE; e++) {
            if (acc[e] > acc[a]) a = e;
        }
        int b = (a == 0) ? 1 : 0;
#pragma unroll
        for (int e = 0; e < NE; e++) {
            if (e != a && acc[e] > acc[b]) b = e;
        }

        float eb = __expf(acc[b] - acc[a]);
        float inv = 1.f / (1.f + eb);
        g_sw[s] = inv;
        g_sw[S_TOK + s] = eb * inv;

        int pa = atomicAdd(&g_count[a], 1);
        g_list[a][pa] = s;
        int pb = atomicAdd(&g_count[b], 1);
        g_list[b][pb] = S_TOK + s;
    }
}

// ---------------------------------------------------------------------------
// tensor-core + cp.async helpers
// ---------------------------------------------------------------------------
__device__ __forceinline__ void ldsm_x4(unsigned& r0, unsigned& r1,
                                        unsigned& r2, unsigned& r3,
                                        const void* p) {
    unsigned a = (unsigned)__cvta_generic_to_shared(p);
    asm volatile("ldmatrix.sync.aligned.m8n8.x4.shared.b16 {%0,%1,%2,%3}, [%4];\n"
                 : "=r"(r0), "=r"(r1), "=r"(r2), "=r"(r3) : "r"(a));
}

__device__ __forceinline__ void ldsm_x4_t(unsigned& r0, unsigned& r1,
                                          unsigned& r2, unsigned& r3,
                                          const void* p) {
    unsigned a = (unsigned)__cvta_generic_to_shared(p);
    asm volatile("ldmatrix.sync.aligned.m8n8.x4.trans.shared.b16 {%0,%1,%2,%3}, [%4];\n"
                 : "=r"(r0), "=r"(r1), "=r"(r2), "=r"(r3) : "r"(a));
}

__device__ __forceinline__ void mma16816(float* c, const unsigned* a, const unsigned* b) {
    asm volatile(
        "mma.sync.aligned.m16n8k16.row.col.f32.f16.f16.f32 "
        "{%0,%1,%2,%3}, {%4,%5,%6,%7}, {%8,%9}, {%0,%1,%2,%3};\n"
        : "+f"(c[0]), "+f"(c[1]), "+f"(c[2]), "+f"(c[3])
        : "r"(a[0]), "r"(a[1]), "r"(a[2]), "r"(a[3]), "r"(b[0]), "r"(b[1]));
}

__device__ __forceinline__ void cp_async16(void* smem_ptr, const void* gptr, bool valid) {
    unsigned saddr = (unsigned)__cvta_generic_to_shared(smem_ptr);
    int sz = valid ? 16 : 0;
    asm volatile("cp.async.cg.shared.global [%0], [%1], 16, %2;\n"
                 :: "r"(saddr), "l"(gptr), "r"(sz));
}
__device__ __forceinline__ void cp_commit() {
    asm volatile("cp.async.commit_group;\n");
}
template<int N>
__device__ __forceinline__ void cp_wait() {
    asm volatile("cp.async.wait_group %0;\n" :: "n"(N));
}

// ---------------------------------------------------------------------------
// Grouped GEMM, 128x128x64 tile, 64x32 warp tiles, 2-stage pipeline, 2 CTA/SM.
//   GEMM1 (+FUSECONV): A = g_xh[slot & (S-1)], W = g_w1h -> relu -> g_h (half);
//                      extra grid-x blocks convert W2 f32->f16 meanwhile.
//   GEMM2: A = g_h[slot], W = g_w2h -> w*(.+b2) atomicAdd -> out
// ---------------------------------------------------------------------------
template<int KDIM, int NDIM, bool GEMM1, bool FUSECONV>
__global__ void __launch_bounds__(256, 2) moe_gemm(const float* __restrict__ bias,
                                                   float* __restrict__ out,
                                                   const float* __restrict__ wsrc) {
    constexpr int NTX = NDIM / BN;
    constexpr int A_ST_ELEM = BM * ASTR;
    constexpr int B_ST_ELEM = BK * BSTR;

    if (FUSECONV && blockIdx.x >= NTX) {
        // W2 conversion side-channel (runs concurrently with GEMM1 compute)
        const int cid = ((blockIdx.x - NTX) * gridDim.y + blockIdx.y) * gridDim.z + blockIdx.z;
        const int t0 = cid * 256 + threadIdx.x;
        const int NT = W2_XTRA * 64 * NE * 256;
        for (int i = t0; i < NW4; i += NT) {
            ((uint2*)g_w2h)[i] = cvt4(((const float4*)wsrc)[i]);
        }
        return;
    }

    const int e = blockIdx.z;
    const int cnt = g_count[e];
    const int row0 = blockIdx.y * BM;
    if (row0 >= cnt) return;
    const int f0 = blockIdx.x * BN;

    extern __shared__ __half dyn[];
    __half* Asb = dyn;                        // [2][BM][ASTR]
    __half* Bsb = dyn + 2 * A_ST_ELEM;        // [2][BK][BSTR]
    __shared__ int rows_s[BM];

    const int tid = threadIdx.x;
    const int lane = tid & 31;
    const int wid = tid >> 5;
    const int wm = (wid >> 2) * 64;
    const int wn = (wid & 3) * 32;

    if (tid < BM) {
        int r = row0 + tid;
        rows_s[tid] = (r < cnt) ? g_list[e][r] : -1;
    }
    __syncthreads();

    const __half* Ab = GEMM1 ? g_xh : g_h;
    const __half* Wb = (GEMM1 ? g_w1h : g_w2h) + (size_t)e * KDIM * NDIM;

    int a_r[4], a_kq[4], a_slot[4];
#pragma unroll
    for (int l = 0; l < 4; l++) {
        int u = tid + l * 256;
        a_r[l] = u >> 3;
        a_kq[l] = u & 7;
        a_slot[l] = rows_s[a_r[l]];
    }
    int b_kr[4], b_cq[4];
#pragma unroll
    for (int l = 0; l < 4; l++) {
        int u = tid + l * 256;
        b_kr[l] = u >> 4;
        b_cq[l] = u & 15;
    }

    const int NK = KDIM / BK;

    auto load_tile = [&](int buf, int kt) {
        __half* As = Asb + buf * A_ST_ELEM;
        __half* Bs = Bsb + buf * B_ST_ELEM;
#pragma unroll
        for (int l = 0; l < 4; l++) {
            int slot = a_slot[l];
            const __half* src = Ab;
            bool v = (slot >= 0);
            if (v) {
                int arow = GEMM1 ? (slot & (S_TOK - 1)) : slot;
                src = Ab + (size_t)arow * KDIM + kt + a_kq[l] * 8;
            }
            cp_async16(As + a_r[l] * ASTR + a_kq[l] * 8, src, v);
        }
#pragma unroll
        for (int l = 0; l < 4; l++) {
            const __half* src = Wb + (size_t)(kt + b_kr[l]) * NDIM + f0 + b_cq[l] * 8;
            cp_async16(Bs + b_kr[l] * BSTR + b_cq[l] * 8, src, true);
        }
    };

    float c[4][4][4];
#pragma unroll
    for (int mi = 0; mi < 4; mi++) {
#pragma unroll
        for (int ni = 0; ni < 4; ni++) {
#pragma unroll
            for (int q = 0; q < 4; q++) {
                c[mi][ni][q] = 0.f;
            }
        }
    }

    load_tile(0, 0);
    cp_commit();

    for (int k = 0; k < NK; k++) {
        cp_wait<0>();
        __syncthreads();

        if (k + 1 < NK) {
            load_tile((k + 1) & 1, (k + 1) * BK);
            cp_commit();
        }

        const int buf = k & 1;
        const __half* As = Asb + buf * A_ST_ELEM;
        const __half* Bs = Bsb + buf * B_ST_ELEM;
#pragma unroll
        for (int kc = 0; kc < BK; kc += 16) {
            unsigned af[4][4];
            unsigned bf[4][2];
#pragma unroll
            for (int mi = 0; mi < 4; mi++) {
                ldsm_x4(af[mi][0], af[mi][1], af[mi][2], af[mi][3],
                        As + (wm + mi * 16 + (lane & 15)) * ASTR + kc + (lane >> 4) * 8);
            }
#pragma unroll
            for (int nj = 0; nj < 2; nj++) {
                ldsm_x4_t(bf[2 * nj][0], bf[2 * nj][1],
                          bf[2 * nj + 1][0], bf[2 * nj + 1][1],
                          Bs + (kc + (lane & 15)) * BSTR + wn + nj * 16 + (lane >> 4) * 8);
            }
#pragma unroll
            for (int mi = 0; mi < 4; mi++) {
#pragma unroll
                for (int ni = 0; ni < 4; ni++) {
                    mma16816(c[mi][ni], af[mi], bf[ni]);
                }
            }
        }
    }

    // epilogue
    const float* be = bias + (size_t)e * NDIM + f0;
    float bias0[4];
    float bias1[4];
#pragma unroll
    for (int ni = 0; ni < 4; ni++) {
        int col = wn + ni * 8 + (lane & 3) * 2;
        bias0[ni] = be[col];
        bias1[ni] = be[col + 1];
    }
#pragma unroll
    for (int mi = 0; mi < 4; mi++) {
#pragma unroll
        for (int hr = 0; hr < 2; hr++) {
            int rr = wm + mi * 16 + hr * 8 + (lane >> 2);
            int slot = rows_s[rr];
            if (slot >= 0) {
                if (GEMM1) {
                    __half* hp = g_h + (size_t)slot * NDIM + f0;
#pragma unroll
                    for (int ni = 0; ni < 4; ni++) {
                        int col = wn + ni * 8 + (lane & 3) * 2;
                        float v0 = fmaxf(c[mi][ni][hr * 2 + 0] + bias0[ni], 0.f);
                        float v1 = fmaxf(c[mi][ni][hr * 2 + 1] + bias1[ni], 0.f);
                        *(__half2*)(hp + col) = __floats2half2_rn(v0, v1);
                    }
                } else {
                    int tok = slot & (S_TOK - 1);
                    float w = g_sw[slot];
                    float* op = out + (size_t)tok * DM + f0;
#pragma unroll
                    for (int ni = 0; ni < 4; ni++) {
                        int col = wn + ni * 8 + (lane & 3) * 2;
                        atomicAdd(op + col,     w * (c[mi][ni][hr * 2 + 0] + bias0[ni]));
                        atomicAdd(op + col + 1, w * (c[mi][ni][hr * 2 + 1] + bias1[ni]));
                    }
                }
            }
        }
    }
}

// ---------------------------------------------------------------------------
extern "C" void kernel_launch(void* const* d_in, const int* in_sizes, int n_in,
                              void* d_out, int out_size) {
    const float* x  = (const float*)d_in[0];
    const float* Wg = (const float*)d_in[1];
    const float* W1 = (const float*)d_in[2];
    const float* b1 = (const float*)d_in[3];
    const float* W2 = (const float*)d_in[4];
    const float* b2 = (const float*)d_in[5];
    float* out = (float*)d_out;

    const int smem = 2 * (BM * ASTR + BK * BSTR) * 2;   // 71680 B
    cudaFuncSetAttribute((const void*)moe_gemm<DM, DF, true, true>,
                         cudaFuncAttributeMaxDynamicSharedMemorySize, smem);
    cudaFuncSetAttribute((const void*)moe_gemm<DF, DM, false, false>,
                         cudaFuncAttributeMaxDynamicSharedMemorySize, smem);

    zero_counts_kernel<<<1, 32>>>();
    gate_prep_kernel<<<GATE_BLKS + CONV_BLKS, 256>>>(x, Wg, W1, out);
    moe_gemm<DM, DF, true, true>
        <<<dim3(DF / BN + W2_XTRA, NSLOT / BM, NE), 256, smem>>>(b1, out, W2);
    moe_gemm<DF, DM, false, false>
        <<<dim3(DM / BN, NSLOT / BM, NE), 256, smem>>>(b2, out, nullptr);
}